// round 16
// baseline (speedup 1.0000x reference)
#include <cuda_runtime.h>
#include <cuda_fp16.h>
#include <math.h>

#define B_  8
#define T_  10
#define N_  50
#define IN_ 6
#define H_  256
#define K_  4
#define E_  2450           // N*(N-1)
#define BN  400            // B*N
#define BE  19600          // B*E
#define HH  (H_ * H_)

// ---------------- scratch (device globals) ----------------------------------
__device__ float g_hidden[BN * H_];
__device__ __half g_hidden_h[BN * H_];
__device__ float g_ins[BN * IN_];
__device__ __half g_Uh[6 * BN * H_];        // fp16 Ur/Us
__device__ __half g_M1h[3 * BE * H_];       // fp16 first-layer tanh
__device__ __half g_msgs3h[3 * BE * H_];    // fp16 per-type weighted messages
__device__ __half g_agg_h[BN * H_];
__device__ __half g_p1h[BN * H_];
__device__ float g_p2[BN * H_];

// fp16 weights (converted once per launch)
__device__ __half g_w1h[6 * HH];            // [z][n][k]
__device__ __half g_w2h[3 * HH];            // [type-1][n][k]
__device__ __half g_whh3[3 * HH];           // hr,hi,hh
__device__ __half g_wo1h[HH];
__device__ __half g_wo2h[HH];
__device__ __half g_b1h[3 * H_];

// ---------------- helpers -----------------------------------------------------
__device__ __forceinline__ float tanh_fast(float x) {
    float r; asm("tanh.approx.f32 %0, %1;" : "=f"(r) : "f"(x)); return r;
}
__device__ __forceinline__ float sigmoid_fast(float x) {
    return 0.5f * tanh_fast(0.5f * x) + 0.5f;
}
__device__ __forceinline__ unsigned tanh2(unsigned x) {
    unsigned r; asm("tanh.approx.f16x2 %0, %1;" : "=r"(r) : "r"(x)); return r;
}
__device__ __forceinline__ unsigned h2pack(float lo, float hi) {
    unsigned r;
    asm("cvt.rn.f16x2.f32 %0, %1, %2;" : "=r"(r) : "f"(hi), "f"(lo));
    return r;
}
__device__ __forceinline__ unsigned hadd2u(unsigned a, unsigned b) {
    __half2 r = __hadd2(*reinterpret_cast<__half2*>(&a),
                        *reinterpret_cast<__half2*>(&b));
    return *reinterpret_cast<unsigned*>(&r);
}
__device__ __forceinline__ void mma16(float c[4], const unsigned a[4],
                                      unsigned b0, unsigned b1) {
    asm volatile(
        "mma.sync.aligned.m16n8k16.row.col.f32.f16.f16.f32 "
        "{%0,%1,%2,%3}, {%4,%5,%6,%7}, {%8,%9}, {%0,%1,%2,%3};"
        : "+f"(c[0]), "+f"(c[1]), "+f"(c[2]), "+f"(c[3])
        : "r"(a[0]), "r"(a[1]), "r"(a[2]), "r"(a[3]), "r"(b0), "r"(b1));
}
__device__ __forceinline__ void ldsm4(unsigned& r0, unsigned& r1,
                                      unsigned& r2, unsigned& r3, unsigned addr) {
    asm volatile("ldmatrix.sync.aligned.m8n8.x4.shared.b16 {%0,%1,%2,%3}, [%4];"
                 : "=r"(r0), "=r"(r1), "=r"(r2), "=r"(r3) : "r"(addr));
}
__device__ __forceinline__ unsigned su32(const void* p) {
    return (unsigned)__cvta_generic_to_shared(p);
}
__device__ __forceinline__ void cp16(unsigned dst, const void* src) {
    asm volatile("cp.async.ca.shared.global [%0], [%1], 16;" :: "r"(dst), "l"(src));
}
__device__ __forceinline__ void cp_commit() { asm volatile("cp.async.commit_group;"); }
__device__ __forceinline__ void cp_wait1() { asm volatile("cp.async.wait_group 1;"); }
__device__ __forceinline__ void cp_wait0() { asm volatile("cp.async.wait_group 0;"); }

#define A_LOFF(lane, wm0) ((unsigned)(((wm0) + ((lane) & 15)) * 48 + (((lane) >> 4) << 4)))
#define W_LOFF(lane, wn0) ((unsigned)((((wn0) + (((lane) & 7) | (((lane) >> 4) << 3))) * 48) + ((((lane) >> 3) & 1) << 4)))

// ---------------- one-time fp16 weight conversion ------------------------------
__global__ void cvt_weights(const float* __restrict__ msg_w1,
                            const float* __restrict__ msg_w2,
                            const float* __restrict__ w_hr,
                            const float* __restrict__ w_hi,
                            const float* __restrict__ w_hh,
                            const float* __restrict__ w_o1,
                            const float* __restrict__ w_o2,
                            const float* __restrict__ msg_b1) {
    int idx = blockIdx.x * blockDim.x + threadIdx.x;
    if (idx < 6 * HH) {
        int z = idx / HH, r = idx - z * HH;
        int n = r / H_, k = r - n * H_;
        int it = z >> 1, rs = z & 1;
        g_w1h[idx] = __float2half(
            msg_w1[(size_t)(it + 1) * H_ * 2 * H_ + (size_t)n * 2 * H_ + rs * H_ + k]);
    }
    if (idx < 3 * HH) {
        int i = idx / HH, r = idx - i * HH;
        g_w2h[idx] = __float2half(msg_w2[(size_t)(i + 1) * HH + r]);
    }
    if (idx < HH) {
        g_whh3[idx]          = __float2half(w_hr[idx]);
        g_whh3[HH + idx]     = __float2half(w_hi[idx]);
        g_whh3[2 * HH + idx] = __float2half(w_hh[idx]);
        g_wo1h[idx] = __float2half(w_o1[idx]);
        g_wo2h[idx] = __float2half(w_o2[idx]);
    }
    if (idx < 3 * H_) {
        int z = idx / H_, h = idx - z * H_;
        g_b1h[idx] = __float2half(msg_b1[(size_t)(z + 1) * H_ + h]);
    }
}

// ---------------- fp16 GEMM tile: 64x128, 128 threads --------------------------
__device__ void tc16_tile(
    const __half* __restrict__ A, int lda,
    const __half* __restrict__ W, int ldw,
    const float* __restrict__ bias,
    float* __restrict__ Cf, __half* __restrict__ Ch, int ldc,
    int M, int row0, int col0, int act)
{
    __shared__ unsigned As[3][64][12];
    __shared__ unsigned Ws[3][128][12];

    const int tid = threadIdx.x;
    const int lane = tid & 31, wid = tid >> 5;
    const int gid = lane >> 2, tig = lane & 3;
    const int wm0 = (wid >> 1) * 32, wn0 = (wid & 1) * 64;
    const int ar = tid >> 1, ap = tid & 1;

    int arow = row0 + ar; if (arow >= M) arow = M - 1;
    const __half* Apt = A + (size_t)arow * lda + ap * 8;
    const __half* Wpt = W + (size_t)(col0 + tid) * ldw;

    const unsigned asA = su32(&As[0][0][0]);
    const unsigned asW = su32(&Ws[0][0][0]);
    const unsigned aoff0 = A_LOFF(lane, wm0);
    const unsigned aoff1 = A_LOFF(lane, wm0 + 16);
    const unsigned woff  = W_LOFF(lane, wn0);

#pragma unroll
    for (int p = 0; p < 2; p++) {
        cp16(su32(&As[p][ar][ap * 4]), Apt + p * 16);
        cp16(su32(&Ws[p][tid][0]), Wpt + p * 16);
        cp16(su32(&Ws[p][tid][4]), Wpt + p * 16 + 8);
        cp_commit();
    }

    float acc[2][8][4];
#pragma unroll
    for (int mi = 0; mi < 2; mi++)
#pragma unroll
        for (int ni = 0; ni < 8; ni++)
#pragma unroll
            for (int j = 0; j < 4; j++) acc[mi][ni][j] = 0.f;

#pragma unroll 1
    for (int c = 0; c < 16; c++) {
        if (c + 1 < 16) cp_wait1(); else cp_wait0();
        __syncthreads();
        int cn = c + 2;
        if (cn < 16) {
            int bf = cn % 3;
            cp16(su32(&As[bf][ar][ap * 4]), Apt + cn * 16);
            cp16(su32(&Ws[bf][tid][0]), Wpt + cn * 16);
            cp16(su32(&Ws[bf][tid][4]), Wpt + cn * 16 + 8);
            cp_commit();
        }
        const int b = c % 3;
        const unsigned abase = asA + (unsigned)b * 3072;
        const unsigned wbase = asW + (unsigned)b * 6144 + woff;
        unsigned a0[4], a1[4];
        ldsm4(a0[0], a0[1], a0[2], a0[3], abase + aoff0);
        ldsm4(a1[0], a1[1], a1[2], a1[3], abase + aoff1);
#pragma unroll
        for (int j = 0; j < 4; j++) {
            unsigned b00, b01, b10, b11;
            ldsm4(b00, b01, b10, b11, wbase + (unsigned)j * 768);
            mma16(acc[0][2 * j],     a0, b00, b01);
            mma16(acc[1][2 * j],     a1, b00, b01);
            mma16(acc[0][2 * j + 1], a0, b10, b11);
            mma16(acc[1][2 * j + 1], a1, b10, b11);
        }
    }

#pragma unroll
    for (int mi = 0; mi < 2; mi++) {
        int r = row0 + wm0 + mi * 16 + gid;
#pragma unroll
        for (int ni = 0; ni < 8; ni++) {
            int cb = col0 + wn0 + ni * 8 + tig * 2;
            float b0 = 0.f, b1 = 0.f;
            if (bias) { b0 = bias[cb]; b1 = bias[cb + 1]; }
            float v0 = acc[mi][ni][0] + b0, v1 = acc[mi][ni][1] + b1;
            float v2 = acc[mi][ni][2] + b0, v3 = acc[mi][ni][3] + b1;
            if (act == 1) {
                v0 = fmaxf(v0, 0.f); v1 = fmaxf(v1, 0.f);
                v2 = fmaxf(v2, 0.f); v3 = fmaxf(v3, 0.f);
            }
            if (Cf) {
                if (r < M)     *(float2*)(Cf + (size_t)r * ldc + cb)       = make_float2(v0, v1);
                if (r + 8 < M) *(float2*)(Cf + (size_t)(r + 8) * ldc + cb) = make_float2(v2, v3);
            } else {
                if (r < M)     *(__half2*)(Ch + (size_t)r * ldc + cb)       = __floats2half2_rn(v0, v1);
                if (r + 8 < M) *(__half2*)(Ch + (size_t)(r + 8) * ldc + cb) = __floats2half2_rn(v2, v3);
            }
        }
    }
}

// ---------------- kernels ------------------------------------------------------

__global__ void init_kernel(const float* __restrict__ inputs) {
    int idx = blockIdx.x * blockDim.x + threadIdx.x;
    if (idx < BN * H_) { g_hidden[idx] = 0.f; g_hidden_h[idx] = __float2half(0.f); }
    if (idx < BN * IN_) {
        int row = idx / IN_, c = idx % IN_;
        int b = row / N_, n = row % N_;
        g_ins[idx] = inputs[(((size_t)b * T_ + 0) * N_ + n) * IN_ + c];
    }
}

__global__ __launch_bounds__(128)
void urus_tc(int dummy) {
    int z = blockIdx.z;
    tc16_tile(g_hidden_h, H_, g_w1h + (size_t)z * HH, H_, nullptr,
              nullptr, g_Uh + (size_t)z * BN * H_, H_,
              BN, blockIdx.x * 64, blockIdx.y * 128, 0);
}

// ---- M1h: tanh(Ur[recv]+Us[send]+b1) fp16x2 ----------------------------------
__global__ __launch_bounds__(256)
void m1h_kernel() {
    const int tid = threadIdx.x;
    const int warp = tid >> 5, lane = tid & 31;
    const int row = blockIdx.x * 8 + warp;
    const int z = blockIdx.y;
    int b = row / E_;
    int e = row - b * E_;
    int send = e / 49, rr2 = e - send * 49;
    int recv = rr2 + (rr2 >= send);

    const __half* Ur = g_Uh + ((size_t)(2 * z) * BN + b * N_ + recv) * H_ + lane * 8;
    const __half* Us = g_Uh + ((size_t)(2 * z + 1) * BN + b * N_ + send) * H_ + lane * 8;
    const __half* B1 = g_b1h + (size_t)z * H_ + lane * 8;

    uint4 u = *(const uint4*)Ur;
    uint4 s = *(const uint4*)Us;
    uint4 bb = *(const uint4*)B1;
    uint4 o;
    o.x = tanh2(hadd2u(hadd2u(u.x, s.x), bb.x));
    o.y = tanh2(hadd2u(hadd2u(u.y, s.y), bb.y));
    o.z = tanh2(hadd2u(hadd2u(u.z, s.z), bb.z));
    o.w = tanh2(hadd2u(hadd2u(u.w, s.w), bb.w));
    *(uint4*)(g_M1h + ((size_t)z * BE + row) * H_ + lane * 8) = o;
}

// ======== edge-message GEMM =====================================================
__global__ __launch_bounds__(128, 4)
void msgs_f16_kernel(const float* __restrict__ msg_b2,
                     const float* __restrict__ edges, int t)
{
    __shared__ unsigned As[3][64][12];
    __shared__ unsigned Ws[3][128][12];
    __shared__ float relw[64];
    __shared__ float b2s[128];

    const int tid = threadIdx.x;
    const int lane = tid & 31, wid = tid >> 5;
    const int gid = lane >> 2, tig = lane & 3;
    const int wm0 = (wid >> 1) * 32, wn0 = (wid & 1) * 64;
    const int row0 = blockIdx.x * 64, col0 = blockIdx.y * 128;
    const int z = blockIdx.z, type = z + 1;

    if (tid < 64) {
        int r = row0 + tid;
        int valid = (r < BE);
        if (!valid) r = BE - 1;
        int b = r / E_;
        int e = r - b * E_;
        relw[tid] = valid
            ? edges[(((size_t)b * T_ + t) * E_ + e) * K_ + type] * (1.f / 3.f)
            : 0.f;
    }
    b2s[tid] = msg_b2[(size_t)type * H_ + col0 + tid];

    const int ar = tid >> 1, ap = tid & 1;
    int arow = row0 + ar; if (arow >= BE) arow = BE - 1;
    const __half* Apt = g_M1h + ((size_t)z * BE + arow) * H_ + ap * 8;
    const __half* Wpt = g_w2h + ((size_t)z * H_ + (col0 + tid)) * H_;

    const unsigned asA = su32(&As[0][0][0]);
    const unsigned asW = su32(&Ws[0][0][0]);
    const unsigned aoff0 = A_LOFF(lane, wm0);
    const unsigned aoff1 = A_LOFF(lane, wm0 + 16);
    const unsigned woff  = W_LOFF(lane, wn0);

#pragma unroll
    for (int p = 0; p < 2; p++) {
        cp16(su32(&As[p][ar][ap * 4]), Apt + p * 16);
        cp16(su32(&Ws[p][tid][0]), Wpt + p * 16);
        cp16(su32(&Ws[p][tid][4]), Wpt + p * 16 + 8);
        cp_commit();
    }

    float acc[2][8][4];
#pragma unroll
    for (int mi = 0; mi < 2; mi++)
#pragma unroll
        for (int ni = 0; ni < 8; ni++)
#pragma unroll
            for (int j = 0; j < 4; j++) acc[mi][ni][j] = 0.f;

#pragma unroll 1
    for (int c = 0; c < 16; c++) {
        if (c + 1 < 16) cp_wait1(); else cp_wait0();
        __syncthreads();
        int cn = c + 2;
        if (cn < 16) {
            int bf = cn % 3;
            cp16(su32(&As[bf][ar][ap * 4]), Apt + cn * 16);
            cp16(su32(&Ws[bf][tid][0]), Wpt + cn * 16);
            cp16(su32(&Ws[bf][tid][4]), Wpt + cn * 16 + 8);
            cp_commit();
        }
        const int b = c % 3;
        const unsigned abase = asA + (unsigned)b * 3072;
        const unsigned wbase = asW + (unsigned)b * 6144 + woff;
        unsigned a0[4], a1[4];
        ldsm4(a0[0], a0[1], a0[2], a0[3], abase + aoff0);
        ldsm4(a1[0], a1[1], a1[2], a1[3], abase + aoff1);
#pragma unroll
        for (int j = 0; j < 4; j++) {
            unsigned b00, b01, b10, b11;
            ldsm4(b00, b01, b10, b11, wbase + (unsigned)j * 768);
            mma16(acc[0][2 * j],     a0, b00, b01);
            mma16(acc[1][2 * j],     a1, b00, b01);
            mma16(acc[0][2 * j + 1], a0, b10, b11);
            mma16(acc[1][2 * j + 1], a1, b10, b11);
        }
    }

    __half* Cz = g_msgs3h + (size_t)z * BE * H_;
#pragma unroll
    for (int mi = 0; mi < 2; mi++) {
        int r = row0 + wm0 + mi * 16 + gid;
        __half2 rl0 = __float2half2_rn(relw[wm0 + mi * 16 + gid]);
        __half2 rl1 = __float2half2_rn(relw[wm0 + mi * 16 + gid + 8]);
#pragma unroll
        for (int ni = 0; ni < 8; ni++) {
            int cb = col0 + wn0 + ni * 8 + tig * 2;
            float bb0 = b2s[wn0 + ni * 8 + tig * 2];
            float bb1 = b2s[wn0 + ni * 8 + tig * 2 + 1];
            if (r < BE) {
                unsigned tr = tanh2(h2pack(acc[mi][ni][0] + bb0, acc[mi][ni][1] + bb1));
                *(__half2*)(Cz + (size_t)r * H_ + cb) =
                    __hmul2(*reinterpret_cast<__half2*>(&tr), rl0);
            }
            if (r + 8 < BE) {
                unsigned tr = tanh2(h2pack(acc[mi][ni][2] + bb0, acc[mi][ni][3] + bb1));
                *(__half2*)(Cz + (size_t)(r + 8) * H_ + cb) =
                    __hmul2(*reinterpret_cast<__half2*>(&tr), rl1);
            }
        }
    }
}

// agg: sum 3 fp16 type-buffers over 49 senders -> fp16
__global__ __launch_bounds__(256)
void agg_kernel() {
    __shared__ float part[3][256];
    const int tid = threadIdx.x;
    const int sg = tid >> 6;
    const int hq = tid & 63;
    const int row = blockIdx.x;
    const int b = row / N_, r = row - b * N_;
    float4 s = make_float4(0.f, 0.f, 0.f, 0.f);
#pragma unroll
    for (int z = 0; z < 3; z++) {
        const __half* base = g_msgs3h + ((size_t)z * BE + (size_t)b * E_) * H_ + hq * 4;
        for (int send = sg; send < N_; send += 4) {
            if (send == r) continue;
            int e = send * 49 + r - (r > send);
            uint2 raw = *(const uint2*)(base + (size_t)e * H_);
            float2 f01 = __half22float2(*reinterpret_cast<__half2*>(&raw.x));
            float2 f23 = __half22float2(*reinterpret_cast<__half2*>(&raw.y));
            s.x += f01.x; s.y += f01.y; s.z += f23.x; s.w += f23.y;
        }
    }
    if (sg > 0) *(float4*)&part[sg - 1][hq * 4] = s;
    __syncthreads();
    if (sg == 0) {
        const float4 p0 = *(const float4*)&part[0][hq * 4];
        const float4 p1 = *(const float4*)&part[1][hq * 4];
        const float4 p2 = *(const float4*)&part[2][hq * 4];
        const float inv = 1.f / 49.f;
        float4 o;
        o.x = (s.x + p0.x + p1.x + p2.x) * inv;
        o.y = (s.y + p0.y + p1.y + p2.y) * inv;
        o.z = (s.z + p0.z + p1.z + p2.z) * inv;
        o.w = (s.w + p0.w + p1.w + p2.w) * inv;
        *(__half2*)(g_agg_h + (size_t)row * H_ + hq * 4)     = __floats2half2_rn(o.x, o.y);
        *(__half2*)(g_agg_h + (size_t)row * H_ + hq * 4 + 2) = __floats2half2_rn(o.z, o.w);
    }
}

// ========== fused GRU: 3 hidden-side GEMMs + elementwise, 64x64 tiles ==========
__global__ __launch_bounds__(128)
void gru3_fused(const float* __restrict__ w_ir, const float* __restrict__ b_ir,
                const float* __restrict__ w_ii, const float* __restrict__ b_ii,
                const float* __restrict__ w_in, const float* __restrict__ b_in)
{
    __shared__ unsigned As[3][64][12];
    __shared__ unsigned Ws[3][3][64][12];   // [buf][matrix][row][words]

    const int tid = threadIdx.x;
    const int lane = tid & 31, wid = tid >> 5;
    const int gid = lane >> 2, tig = lane & 3;
    const int wm0 = (wid >> 1) * 32, wn0 = (wid & 1) * 32;
    const int row0 = blockIdx.x * 64, col0 = blockIdx.y * 64;

    // A staging: agg rows
    const int ar = tid >> 1, ap = tid & 1;
    int arow = row0 + ar; if (arow >= BN) arow = BN - 1;
    const __half* Apt = g_agg_h + (size_t)arow * H_ + ap * 8;

    // W staging: rows tid and tid+128 of the 192 (3 matrices x 64 rows)
    const int wr0 = tid;                 // 0..127 -> m = tid>>6, r = tid&63
    const int wr1 = tid + 128;           // 128..255 -> valid if < 192
    const __half* Wp0 = g_whh3 + (size_t)(wr0 >> 6) * HH + (size_t)(col0 + (wr0 & 63)) * H_;
    const __half* Wp1 = g_whh3 + (size_t)(wr1 >> 6) * HH + (size_t)(col0 + (wr1 & 63)) * H_;
    const bool w1v = (wr1 < 192);

    const unsigned asA = su32(&As[0][0][0]);
    const unsigned asW = su32(&Ws[0][0][0][0]);
    const unsigned aoff0 = A_LOFF(lane, wm0);
    const unsigned aoff1 = A_LOFF(lane, wm0 + 16);
    const unsigned woff  = W_LOFF(lane, wn0);
    const unsigned wdst0 = asW + (unsigned)(wr0 >> 6) * 3072 + (unsigned)(wr0 & 63) * 48;
    const unsigned wdst1 = asW + (unsigned)(wr1 >> 6) * 3072 + (unsigned)(wr1 & 63) * 48;

#pragma unroll
    for (int p = 0; p < 2; p++) {
        cp16(su32(&As[p][ar][ap * 4]), Apt + p * 16);
        cp16(wdst0 + (unsigned)p * 9216, Wp0 + p * 16);
        cp16(wdst0 + (unsigned)p * 9216 + 16, Wp0 + p * 16 + 8);
        if (w1v) {
            cp16(wdst1 + (unsigned)p * 9216, Wp1 + p * 16);
            cp16(wdst1 + (unsigned)p * 9216 + 16, Wp1 + p * 16 + 8);
        }
        cp_commit();
    }

    float acc[3][2][4][4];
#pragma unroll
    for (int m = 0; m < 3; m++)
#pragma unroll
        for (int mi = 0; mi < 2; mi++)
#pragma unroll
            for (int ni = 0; ni < 4; ni++)
#pragma unroll
                for (int j = 0; j < 4; j++) acc[m][mi][ni][j] = 0.f;

#pragma unroll 1
    for (int c = 0; c < 16; c++) {
        if (c + 1 < 16) cp_wait1(); else cp_wait0();
        __syncthreads();
        int cn = c + 2;
        if (cn < 16) {
            int bf = cn % 3;
            cp16(su32(&As[bf][ar][ap * 4]), Apt + cn * 16);
            cp16(wdst0 + (unsigned)bf * 9216, Wp0 + cn * 16);
            cp16(wdst0 + (unsigned)bf * 9216 + 16, Wp0 + cn * 16 + 8);
            if (w1v) {
                cp16(wdst1 + (unsigned)bf * 9216, Wp1 + cn * 16);
                cp16(wdst1 + (unsigned)bf * 9216 + 16, Wp1 + cn * 16 + 8);
            }
            cp_commit();
        }
        const int b = c % 3;
        const unsigned abase = asA + (unsigned)b * 3072;
        unsigned a0[4], a1[4];
        ldsm4(a0[0], a0[1], a0[2], a0[3], abase + aoff0);
        ldsm4(a1[0], a1[1], a1[2], a1[3], abase + aoff1);
#pragma unroll
        for (int m = 0; m < 3; m++) {
            const unsigned wbase = asW + (unsigned)b * 9216 + (unsigned)m * 3072 + woff;
#pragma unroll
            for (int j = 0; j < 2; j++) {
                unsigned b00, b01, b10, b11;
                ldsm4(b00, b01, b10, b11, wbase + (unsigned)j * 768);
                mma16(acc[m][0][2 * j],     a0, b00, b01);
                mma16(acc[m][1][2 * j],     a1, b00, b01);
                mma16(acc[m][0][2 * j + 1], a0, b10, b11);
                mma16(acc[m][1][2 * j + 1], a1, b10, b11);
            }
        }
    }

    // ---- GRU elementwise in fragment layout ----
    float insv[4][6];
#pragma unroll
    for (int k = 0; k < 4; k++) {
        int grow = row0 + wm0 + (k >> 1) * 16 + (k & 1) * 8 + gid;
#pragma unroll
        for (int f = 0; f < 6; f++)
            insv[k][f] = (grow < BN) ? g_ins[grow * IN_ + f] : 0.f;
    }
#pragma unroll
    for (int ni = 0; ni < 4; ni++) {
        int c0 = col0 + wn0 + ni * 8 + tig * 2;
        float wr[2][6], wi[2][6], wn[2][6];
#pragma unroll
        for (int f = 0; f < 6; f++) {
            wr[0][f] = w_ir[c0 * 6 + f];       wr[1][f] = w_ir[(c0 + 1) * 6 + f];
            wi[0][f] = w_ii[c0 * 6 + f];       wi[1][f] = w_ii[(c0 + 1) * 6 + f];
            wn[0][f] = w_in[c0 * 6 + f];       wn[1][f] = w_in[(c0 + 1) * 6 + f];
        }
        float br[2] = {b_ir[c0], b_ir[c0 + 1]};
        float bi[2] = {b_ii[c0], b_ii[c0 + 1]};
        float bn[2] = {b_in[c0], b_in[c0 + 1]};
#pragma unroll
        for (int mi = 0; mi < 2; mi++) {
#pragma unroll
            for (int pr = 0; pr < 2; pr++) {
                int rl = wm0 + mi * 16 + pr * 8 + gid;
                int grow = row0 + rl;
                if (grow >= BN) continue;
                int k = mi * 2 + pr;
#pragma unroll
                for (int cc = 0; cc < 2; cc++) {
                    float xr = br[cc], xi = bi[cc], xn = bn[cc];
#pragma unroll
                    for (int f = 0; f < 6; f++) {
                        float iv = insv[k][f];
                        xr += iv * wr[cc][f];
                        xi += iv * wi[cc][f];
                        xn += iv * wn[cc][f];
                    }
                    float aR = acc[0][mi][ni][pr * 2 + cc];
                    float aI = acc[1][mi][ni][pr * 2 + cc];
                    float aH = acc[2][mi][ni][pr * 2 + cc];
                    float r  = sigmoid_fast(xr + aR);
                    float ig = sigmoid_fast(xi + aI);
                    float nn = tanh_fast(xn + r * aH);
                    float old = g_hidden[grow * H_ + c0 + cc];
                    float hnew = (1.f - ig) * nn + ig * old;
                    g_hidden[grow * H_ + c0 + cc] = hnew;
                    g_hidden_h[grow * H_ + c0 + cc] = __float2half(hnew);
                }
            }
        }
    }
}

__global__ __launch_bounds__(128)
void p1_tc(const float* __restrict__ b_o1) {
    tc16_tile(g_hidden_h, H_, g_wo1h, H_, b_o1, nullptr, g_p1h, H_,
              BN, blockIdx.x * 64, blockIdx.y * 128, 1);
}
__global__ __launch_bounds__(128)
void p2_tc(const float* __restrict__ b_o2) {
    tc16_tile(g_p1h, H_, g_wo2h, H_, b_o2, g_p2, nullptr, H_,
              BN, blockIdx.x * 64, blockIdx.y * 128, 1);
}

__global__ void f3_kernel(const float* __restrict__ w_o3,
                          const float* __restrict__ b_o3,
                          float* __restrict__ out, int t) {
    int row = blockIdx.x;
    int w = threadIdx.x >> 5;
    int lane = threadIdx.x & 31;
    const float* pr = g_p2 + (size_t)row * H_;
    const float* wr = w_o3 + (size_t)w * H_;
    float s = 0.f;
    for (int j = lane; j < H_; j += 32) s += pr[j] * wr[j];
#pragma unroll
    for (int off = 16; off; off >>= 1) s += __shfl_down_sync(0xffffffffu, s, off);
    if (lane == 0) {
        int b = row / N_, n = row % N_;
        float v = g_ins[row * IN_ + w] + b_o3[w] + s;
        out[(((size_t)b * T_ + t) * N_ + n) * IN_ + w] = v;
        g_ins[row * IN_ + w] = v;
    }
}

// ---------------- launch ---------------------------------------------------------
extern "C" void kernel_launch(void* const* d_in, const int* in_sizes, int n_in,
                              void* d_out, int out_size) {
    const float* inputs = (const float*)d_in[0];
    const float* edges  = (const float*)d_in[1];
    const float* msg_w1 = (const float*)d_in[2];
    const float* msg_b1 = (const float*)d_in[3];
    const float* msg_w2 = (const float*)d_in[4];
    const float* msg_b2 = (const float*)d_in[5];
    const float* w_hr = (const float*)d_in[6];
    const float* w_hi = (const float*)d_in[7];
    const float* w_hh = (const float*)d_in[8];
    const float* w_ir = (const float*)d_in[9];
    const float* b_ir = (const float*)d_in[10];
    const float* w_ii = (const float*)d_in[11];
    const float* b_ii = (const float*)d_in[12];
    const float* w_in_ = (const float*)d_in[13];
    const float* b_in_ = (const float*)d_in[14];
    const float* w_o1 = (const float*)d_in[15];
    const float* b_o1 = (const float*)d_in[16];
    const float* w_o2 = (const float*)d_in[17];
    const float* b_o2 = (const float*)d_in[18];
    const float* w_o3 = (const float*)d_in[19];
    const float* b_o3 = (const float*)d_in[20];
    float* out = (float*)d_out;

    // one extra stream + two events (r14 configuration: passes teardown check)
    static cudaStream_t s2 = nullptr;
    static cudaEvent_t evF = nullptr, evJ = nullptr;
    if (s2 == nullptr) {
        cudaStreamCreateWithFlags(&s2, cudaStreamNonBlocking);
        cudaEventCreateWithFlags(&evF, cudaEventDisableTiming);
        cudaEventCreateWithFlags(&evJ, cudaEventDisableTiming);
    }

    cvt_weights<<<(6 * HH + 255) / 256, 256>>>(msg_w1, msg_w2, w_hr, w_hi, w_hh,
                                               w_o1, w_o2, msg_b1);
    init_kernel<<<(BN * H_ + 255) / 256, 256>>>(inputs);

    const int rowt = (BE + 63) / 64;  // 307
    for (int t = 0; t < T_; t++) {
        if (t > 0) {
            // output-MLP chain for step t-1 (reads hidden only) on s2
            cudaEventRecord(evF, 0);
            cudaStreamWaitEvent(s2, evF, 0);
            p1_tc<<<dim3(7, 2), 128, 0, s2>>>(b_o1);
            p2_tc<<<dim3(7, 2), 128, 0, s2>>>(b_o2);
            f3_kernel<<<BN, 192, 0, s2>>>(w_o3, b_o3, out, t - 1);
            cudaEventRecord(evJ, s2);
        }
        urus_tc<<<dim3(7, 2, 6), 128>>>(0);
        m1h_kernel<<<dim3(BE / 8, 3), 256>>>();
        msgs_f16_kernel<<<dim3(rowt, 2, 3), 128>>>(msg_b2, edges, t);
        agg_kernel<<<BN, 256>>>();
        if (t > 0) cudaStreamWaitEvent(0, evJ, 0);   // need g_ins (f3) + hidden reads done
        gru3_fused<<<dim3(7, 4), 128>>>(w_ir, b_ir, w_ii, b_ii, w_in_, b_in_);
    }
    // final step's output MLP
    p1_tc<<<dim3(7, 2), 128>>>(b_o1);
    p2_tc<<<dim3(7, 2), 128>>>(b_o2);
    f3_kernel<<<BN, 192>>>(w_o3, b_o3, out, T_ - 1);
}

// round 17
// speedup vs baseline: 1.0658x; 1.0658x over previous
#include <cuda_runtime.h>
#include <cuda_fp16.h>
#include <math.h>

#define B_  8
#define T_  10
#define N_  50
#define IN_ 6
#define H_  256
#define K_  4
#define E_  2450           // N*(N-1)
#define BN  400            // B*N
#define BE  19600          // B*E
#define HH  (H_ * H_)

// ---------------- scratch (device globals) ----------------------------------
__device__ float g_hidden[BN * H_];
__device__ __half g_hidden_h[BN * H_];
__device__ float g_ins[BN * IN_];
__device__ __half g_Uh[6 * BN * H_];        // fp16 Ur/Us
__device__ __half g_M1h[3 * BE * H_];       // fp16 first-layer tanh
__device__ __half g_msgs3h[3 * BE * H_];    // fp16 per-type weighted messages
__device__ __half g_agg_h[BN * H_];
__device__ float g_gru[3 * BN * H_];
__device__ __half g_p1h[BN * H_];
__device__ float g_p2[BN * H_];

// fp16 weights (converted once per launch)
__device__ __half g_w1h[6 * HH];            // [z][n][k]
__device__ __half g_w2h[3 * HH];            // [type-1][n][k]
__device__ __half g_whh3[3 * HH];           // hr,hi,hh
__device__ __half g_wo1h[HH];
__device__ __half g_wo2h[HH];
__device__ __half g_b1h[3 * H_];

// ---------------- helpers -----------------------------------------------------
__device__ __forceinline__ float tanh_fast(float x) {
    float r; asm("tanh.approx.f32 %0, %1;" : "=f"(r) : "f"(x)); return r;
}
__device__ __forceinline__ float sigmoid_fast(float x) {
    return 0.5f * tanh_fast(0.5f * x) + 0.5f;
}
__device__ __forceinline__ unsigned tanh2(unsigned x) {
    unsigned r; asm("tanh.approx.f16x2 %0, %1;" : "=r"(r) : "r"(x)); return r;
}
__device__ __forceinline__ unsigned h2pack(float lo, float hi) {
    unsigned r;
    asm("cvt.rn.f16x2.f32 %0, %1, %2;" : "=r"(r) : "f"(hi), "f"(lo));
    return r;
}
__device__ __forceinline__ unsigned hadd2u(unsigned a, unsigned b) {
    __half2 r = __hadd2(*reinterpret_cast<__half2*>(&a),
                        *reinterpret_cast<__half2*>(&b));
    return *reinterpret_cast<unsigned*>(&r);
}
__device__ __forceinline__ void mma16(float c[4], const unsigned a[4],
                                      unsigned b0, unsigned b1) {
    asm volatile(
        "mma.sync.aligned.m16n8k16.row.col.f32.f16.f16.f32 "
        "{%0,%1,%2,%3}, {%4,%5,%6,%7}, {%8,%9}, {%0,%1,%2,%3};"
        : "+f"(c[0]), "+f"(c[1]), "+f"(c[2]), "+f"(c[3])
        : "r"(a[0]), "r"(a[1]), "r"(a[2]), "r"(a[3]), "r"(b0), "r"(b1));
}
__device__ __forceinline__ void ldsm4(unsigned& r0, unsigned& r1,
                                      unsigned& r2, unsigned& r3, unsigned addr) {
    asm volatile("ldmatrix.sync.aligned.m8n8.x4.shared.b16 {%0,%1,%2,%3}, [%4];"
                 : "=r"(r0), "=r"(r1), "=r"(r2), "=r"(r3) : "r"(addr));
}
__device__ __forceinline__ unsigned su32(const void* p) {
    return (unsigned)__cvta_generic_to_shared(p);
}
__device__ __forceinline__ void cp16(unsigned dst, const void* src) {
    asm volatile("cp.async.ca.shared.global [%0], [%1], 16;" :: "r"(dst), "l"(src));
}
__device__ __forceinline__ void cp_commit() { asm volatile("cp.async.commit_group;"); }
__device__ __forceinline__ void cp_wait1() { asm volatile("cp.async.wait_group 1;"); }
__device__ __forceinline__ void cp_wait0() { asm volatile("cp.async.wait_group 0;"); }

#define A_LOFF(lane, wm0) ((unsigned)(((wm0) + ((lane) & 15)) * 48 + (((lane) >> 4) << 4)))
#define W_LOFF(lane, wn0) ((unsigned)((((wn0) + (((lane) & 7) | (((lane) >> 4) << 3))) * 48) + ((((lane) >> 3) & 1) << 4)))

// ---------------- one-time fp16 weight conversion ------------------------------
__global__ void cvt_weights(const float* __restrict__ msg_w1,
                            const float* __restrict__ msg_w2,
                            const float* __restrict__ w_hr,
                            const float* __restrict__ w_hi,
                            const float* __restrict__ w_hh,
                            const float* __restrict__ w_o1,
                            const float* __restrict__ w_o2,
                            const float* __restrict__ msg_b1) {
    int idx = blockIdx.x * blockDim.x + threadIdx.x;
    if (idx < 6 * HH) {
        int z = idx / HH, r = idx - z * HH;
        int n = r / H_, k = r - n * H_;
        int it = z >> 1, rs = z & 1;
        g_w1h[idx] = __float2half(
            msg_w1[(size_t)(it + 1) * H_ * 2 * H_ + (size_t)n * 2 * H_ + rs * H_ + k]);
    }
    if (idx < 3 * HH) {
        int i = idx / HH, r = idx - i * HH;
        g_w2h[idx] = __float2half(msg_w2[(size_t)(i + 1) * HH + r]);
    }
    if (idx < HH) {
        g_whh3[idx]          = __float2half(w_hr[idx]);
        g_whh3[HH + idx]     = __float2half(w_hi[idx]);
        g_whh3[2 * HH + idx] = __float2half(w_hh[idx]);
        g_wo1h[idx] = __float2half(w_o1[idx]);
        g_wo2h[idx] = __float2half(w_o2[idx]);
    }
    if (idx < 3 * H_) {
        int z = idx / H_, h = idx - z * H_;
        g_b1h[idx] = __float2half(msg_b1[(size_t)(z + 1) * H_ + h]);
    }
}

// ---------------- fp16 GEMM tile: 64x128, 128 threads --------------------------
__device__ void tc16_tile(
    const __half* __restrict__ A, int lda,
    const __half* __restrict__ W, int ldw,
    const float* __restrict__ bias,
    float* __restrict__ Cf, __half* __restrict__ Ch, int ldc,
    int M, int row0, int col0, int act)
{
    __shared__ unsigned As[3][64][12];
    __shared__ unsigned Ws[3][128][12];

    const int tid = threadIdx.x;
    const int lane = tid & 31, wid = tid >> 5;
    const int gid = lane >> 2, tig = lane & 3;
    const int wm0 = (wid >> 1) * 32, wn0 = (wid & 1) * 64;
    const int ar = tid >> 1, ap = tid & 1;

    int arow = row0 + ar; if (arow >= M) arow = M - 1;
    const __half* Apt = A + (size_t)arow * lda + ap * 8;
    const __half* Wpt = W + (size_t)(col0 + tid) * ldw;

    const unsigned asA = su32(&As[0][0][0]);
    const unsigned asW = su32(&Ws[0][0][0]);
    const unsigned aoff0 = A_LOFF(lane, wm0);
    const unsigned aoff1 = A_LOFF(lane, wm0 + 16);
    const unsigned woff  = W_LOFF(lane, wn0);

#pragma unroll
    for (int p = 0; p < 2; p++) {
        cp16(su32(&As[p][ar][ap * 4]), Apt + p * 16);
        cp16(su32(&Ws[p][tid][0]), Wpt + p * 16);
        cp16(su32(&Ws[p][tid][4]), Wpt + p * 16 + 8);
        cp_commit();
    }

    float acc[2][8][4];
#pragma unroll
    for (int mi = 0; mi < 2; mi++)
#pragma unroll
        for (int ni = 0; ni < 8; ni++)
#pragma unroll
            for (int j = 0; j < 4; j++) acc[mi][ni][j] = 0.f;

#pragma unroll 1
    for (int c = 0; c < 16; c++) {
        if (c + 1 < 16) cp_wait1(); else cp_wait0();
        __syncthreads();
        int cn = c + 2;
        if (cn < 16) {
            int bf = cn % 3;
            cp16(su32(&As[bf][ar][ap * 4]), Apt + cn * 16);
            cp16(su32(&Ws[bf][tid][0]), Wpt + cn * 16);
            cp16(su32(&Ws[bf][tid][4]), Wpt + cn * 16 + 8);
            cp_commit();
        }
        const int b = c % 3;
        const unsigned abase = asA + (unsigned)b * 3072;
        const unsigned wbase = asW + (unsigned)b * 6144 + woff;
        unsigned a0[4], a1[4];
        ldsm4(a0[0], a0[1], a0[2], a0[3], abase + aoff0);
        ldsm4(a1[0], a1[1], a1[2], a1[3], abase + aoff1);
#pragma unroll
        for (int j = 0; j < 4; j++) {
            unsigned b00, b01, b10, b11;
            ldsm4(b00, b01, b10, b11, wbase + (unsigned)j * 768);
            mma16(acc[0][2 * j],     a0, b00, b01);
            mma16(acc[1][2 * j],     a1, b00, b01);
            mma16(acc[0][2 * j + 1], a0, b10, b11);
            mma16(acc[1][2 * j + 1], a1, b10, b11);
        }
    }

#pragma unroll
    for (int mi = 0; mi < 2; mi++) {
        int r = row0 + wm0 + mi * 16 + gid;
#pragma unroll
        for (int ni = 0; ni < 8; ni++) {
            int cb = col0 + wn0 + ni * 8 + tig * 2;
            float b0 = 0.f, b1 = 0.f;
            if (bias) { b0 = bias[cb]; b1 = bias[cb + 1]; }
            float v0 = acc[mi][ni][0] + b0, v1 = acc[mi][ni][1] + b1;
            float v2 = acc[mi][ni][2] + b0, v3 = acc[mi][ni][3] + b1;
            if (act == 1) {
                v0 = fmaxf(v0, 0.f); v1 = fmaxf(v1, 0.f);
                v2 = fmaxf(v2, 0.f); v3 = fmaxf(v3, 0.f);
            }
            if (Cf) {
                if (r < M)     *(float2*)(Cf + (size_t)r * ldc + cb)       = make_float2(v0, v1);
                if (r + 8 < M) *(float2*)(Cf + (size_t)(r + 8) * ldc + cb) = make_float2(v2, v3);
            } else {
                if (r < M)     *(__half2*)(Ch + (size_t)r * ldc + cb)       = __floats2half2_rn(v0, v1);
                if (r + 8 < M) *(__half2*)(Ch + (size_t)(r + 8) * ldc + cb) = __floats2half2_rn(v2, v3);
            }
        }
    }
}

// ---------------- kernels ------------------------------------------------------

__global__ void init_kernel(const float* __restrict__ inputs) {
    int idx = blockIdx.x * blockDim.x + threadIdx.x;
    if (idx < BN * H_) { g_hidden[idx] = 0.f; g_hidden_h[idx] = __float2half(0.f); }
    if (idx < BN * IN_) {
        int row = idx / IN_, c = idx % IN_;
        int b = row / N_, n = row % N_;
        g_ins[idx] = inputs[(((size_t)b * T_ + 0) * N_ + n) * IN_ + c];
    }
}

__global__ __launch_bounds__(128, 4)
void urus_tc(int dummy) {
    int z = blockIdx.z;
    tc16_tile(g_hidden_h, H_, g_w1h + (size_t)z * HH, H_, nullptr,
              nullptr, g_Uh + (size_t)z * BN * H_, H_,
              BN, blockIdx.x * 64, blockIdx.y * 128, 0);
}

// ---- M1h: tanh(Ur[recv]+Us[send]+b1) fp16x2 ----------------------------------
__global__ __launch_bounds__(256)
void m1h_kernel() {
    const int tid = threadIdx.x;
    const int warp = tid >> 5, lane = tid & 31;
    const int row = blockIdx.x * 8 + warp;
    const int z = blockIdx.y;
    int b = row / E_;
    int e = row - b * E_;
    int send = e / 49, rr2 = e - send * 49;
    int recv = rr2 + (rr2 >= send);

    const __half* Ur = g_Uh + ((size_t)(2 * z) * BN + b * N_ + recv) * H_ + lane * 8;
    const __half* Us = g_Uh + ((size_t)(2 * z + 1) * BN + b * N_ + send) * H_ + lane * 8;
    const __half* B1 = g_b1h + (size_t)z * H_ + lane * 8;

    uint4 u = *(const uint4*)Ur;
    uint4 s = *(const uint4*)Us;
    uint4 bb = *(const uint4*)B1;
    uint4 o;
    o.x = tanh2(hadd2u(hadd2u(u.x, s.x), bb.x));
    o.y = tanh2(hadd2u(hadd2u(u.y, s.y), bb.y));
    o.z = tanh2(hadd2u(hadd2u(u.z, s.z), bb.z));
    o.w = tanh2(hadd2u(hadd2u(u.w, s.w), bb.w));
    *(uint4*)(g_M1h + ((size_t)z * BE + row) * H_ + lane * 8) = o;
}

// ======== edge-message GEMM =====================================================
__global__ __launch_bounds__(128, 4)
void msgs_f16_kernel(const float* __restrict__ msg_b2,
                     const float* __restrict__ edges, int t)
{
    __shared__ unsigned As[3][64][12];
    __shared__ unsigned Ws[3][128][12];
    __shared__ float relw[64];
    __shared__ float b2s[128];

    const int tid = threadIdx.x;
    const int lane = tid & 31, wid = tid >> 5;
    const int gid = lane >> 2, tig = lane & 3;
    const int wm0 = (wid >> 1) * 32, wn0 = (wid & 1) * 64;
    const int row0 = blockIdx.x * 64, col0 = blockIdx.y * 128;
    const int z = blockIdx.z, type = z + 1;

    if (tid < 64) {
        int r = row0 + tid;
        int valid = (r < BE);
        if (!valid) r = BE - 1;
        int b = r / E_;
        int e = r - b * E_;
        relw[tid] = valid
            ? edges[(((size_t)b * T_ + t) * E_ + e) * K_ + type] * (1.f / 3.f)
            : 0.f;
    }
    b2s[tid] = msg_b2[(size_t)type * H_ + col0 + tid];

    const int ar = tid >> 1, ap = tid & 1;
    int arow = row0 + ar; if (arow >= BE) arow = BE - 1;
    const __half* Apt = g_M1h + ((size_t)z * BE + arow) * H_ + ap * 8;
    const __half* Wpt = g_w2h + ((size_t)z * H_ + (col0 + tid)) * H_;

    const unsigned asA = su32(&As[0][0][0]);
    const unsigned asW = su32(&Ws[0][0][0]);
    const unsigned aoff0 = A_LOFF(lane, wm0);
    const unsigned aoff1 = A_LOFF(lane, wm0 + 16);
    const unsigned woff  = W_LOFF(lane, wn0);

#pragma unroll
    for (int p = 0; p < 2; p++) {
        cp16(su32(&As[p][ar][ap * 4]), Apt + p * 16);
        cp16(su32(&Ws[p][tid][0]), Wpt + p * 16);
        cp16(su32(&Ws[p][tid][4]), Wpt + p * 16 + 8);
        cp_commit();
    }

    float acc[2][8][4];
#pragma unroll
    for (int mi = 0; mi < 2; mi++)
#pragma unroll
        for (int ni = 0; ni < 8; ni++)
#pragma unroll
            for (int j = 0; j < 4; j++) acc[mi][ni][j] = 0.f;

#pragma unroll 1
    for (int c = 0; c < 16; c++) {
        if (c + 1 < 16) cp_wait1(); else cp_wait0();
        __syncthreads();
        int cn = c + 2;
        if (cn < 16) {
            int bf = cn % 3;
            cp16(su32(&As[bf][ar][ap * 4]), Apt + cn * 16);
            cp16(su32(&Ws[bf][tid][0]), Wpt + cn * 16);
            cp16(su32(&Ws[bf][tid][4]), Wpt + cn * 16 + 8);
            cp_commit();
        }
        const int b = c % 3;
        const unsigned abase = asA + (unsigned)b * 3072;
        const unsigned wbase = asW + (unsigned)b * 6144 + woff;
        unsigned a0[4], a1[4];
        ldsm4(a0[0], a0[1], a0[2], a0[3], abase + aoff0);
        ldsm4(a1[0], a1[1], a1[2], a1[3], abase + aoff1);
#pragma unroll
        for (int j = 0; j < 4; j++) {
            unsigned b00, b01, b10, b11;
            ldsm4(b00, b01, b10, b11, wbase + (unsigned)j * 768);
            mma16(acc[0][2 * j],     a0, b00, b01);
            mma16(acc[1][2 * j],     a1, b00, b01);
            mma16(acc[0][2 * j + 1], a0, b10, b11);
            mma16(acc[1][2 * j + 1], a1, b10, b11);
        }
    }

    __half* Cz = g_msgs3h + (size_t)z * BE * H_;
#pragma unroll
    for (int mi = 0; mi < 2; mi++) {
        int r = row0 + wm0 + mi * 16 + gid;
        __half2 rl0 = __float2half2_rn(relw[wm0 + mi * 16 + gid]);
        __half2 rl1 = __float2half2_rn(relw[wm0 + mi * 16 + gid + 8]);
#pragma unroll
        for (int ni = 0; ni < 8; ni++) {
            int cb = col0 + wn0 + ni * 8 + tig * 2;
            float bb0 = b2s[wn0 + ni * 8 + tig * 2];
            float bb1 = b2s[wn0 + ni * 8 + tig * 2 + 1];
            if (r < BE) {
                unsigned tr = tanh2(h2pack(acc[mi][ni][0] + bb0, acc[mi][ni][1] + bb1));
                *(__half2*)(Cz + (size_t)r * H_ + cb) =
                    __hmul2(*reinterpret_cast<__half2*>(&tr), rl0);
            }
            if (r + 8 < BE) {
                unsigned tr = tanh2(h2pack(acc[mi][ni][2] + bb0, acc[mi][ni][3] + bb1));
                *(__half2*)(Cz + (size_t)(r + 8) * H_ + cb) =
                    __hmul2(*reinterpret_cast<__half2*>(&tr), rl1);
            }
        }
    }
}

// agg: sum 3 fp16 type-buffers over 49 senders -> fp16
__global__ __launch_bounds__(256)
void agg_kernel() {
    __shared__ float part[3][256];
    const int tid = threadIdx.x;
    const int sg = tid >> 6;
    const int hq = tid & 63;
    const int row = blockIdx.x;
    const int b = row / N_, r = row - b * N_;
    float4 s = make_float4(0.f, 0.f, 0.f, 0.f);
#pragma unroll
    for (int z = 0; z < 3; z++) {
        const __half* base = g_msgs3h + ((size_t)z * BE + (size_t)b * E_) * H_ + hq * 4;
        for (int send = sg; send < N_; send += 4) {
            if (send == r) continue;
            int e = send * 49 + r - (r > send);
            uint2 raw = *(const uint2*)(base + (size_t)e * H_);
            float2 f01 = __half22float2(*reinterpret_cast<__half2*>(&raw.x));
            float2 f23 = __half22float2(*reinterpret_cast<__half2*>(&raw.y));
            s.x += f01.x; s.y += f01.y; s.z += f23.x; s.w += f23.y;
        }
    }
    if (sg > 0) *(float4*)&part[sg - 1][hq * 4] = s;
    __syncthreads();
    if (sg == 0) {
        const float4 p0 = *(const float4*)&part[0][hq * 4];
        const float4 p1 = *(const float4*)&part[1][hq * 4];
        const float4 p2 = *(const float4*)&part[2][hq * 4];
        const float inv = 1.f / 49.f;
        float4 o;
        o.x = (s.x + p0.x + p1.x + p2.x) * inv;
        o.y = (s.y + p0.y + p1.y + p2.y) * inv;
        o.z = (s.z + p0.z + p1.z + p2.z) * inv;
        o.w = (s.w + p0.w + p1.w + p2.w) * inv;
        *(__half2*)(g_agg_h + (size_t)row * H_ + hq * 4)     = __floats2half2_rn(o.x, o.y);
        *(__half2*)(g_agg_h + (size_t)row * H_ + hq * 4 + 2) = __floats2half2_rn(o.z, o.w);
    }
}

__global__ __launch_bounds__(128, 4)
void gru_tc(int dummy) {
    int z = blockIdx.z;
    tc16_tile(g_agg_h, H_, g_whh3 + (size_t)z * HH, H_, nullptr,
              g_gru + (size_t)z * BN * H_, nullptr, H_,
              BN, blockIdx.x * 64, blockIdx.y * 128, 0);
}

__global__ void gruew_kernel(const float* __restrict__ w_ir, const float* __restrict__ b_ir,
                             const float* __restrict__ w_ii, const float* __restrict__ b_ii,
                             const float* __restrict__ w_in, const float* __restrict__ b_in) {
    int idx = blockIdx.x * blockDim.x + threadIdx.x;
    if (idx >= BN * H_) return;
    int row = idx / H_, h = idx - row * H_;
    float xr = b_ir[h], xi = b_ii[h], xn = b_in[h];
#pragma unroll
    for (int f = 0; f < IN_; f++) {
        float iv = g_ins[row * IN_ + f];
        xr += iv * w_ir[h * IN_ + f];
        xi += iv * w_ii[h * IN_ + f];
        xn += iv * w_in[h * IN_ + f];
    }
    float ar = g_gru[idx];
    float ai = g_gru[BN * H_ + idx];
    float ah = g_gru[2 * BN * H_ + idx];
    float r  = sigmoid_fast(xr + ar);
    float ig = sigmoid_fast(xi + ai);
    float nn = tanh_fast(xn + r * ah);
    float hnew = (1.f - ig) * nn + ig * g_hidden[idx];
    g_hidden[idx] = hnew;
    g_hidden_h[idx] = __float2half(hnew);
}

__global__ __launch_bounds__(128, 4)
void p1_tc(const float* __restrict__ b_o1) {
    tc16_tile(g_hidden_h, H_, g_wo1h, H_, b_o1, nullptr, g_p1h, H_,
              BN, blockIdx.x * 64, blockIdx.y * 128, 1);
}
__global__ __launch_bounds__(128, 4)
void p2_tc(const float* __restrict__ b_o2) {
    tc16_tile(g_p1h, H_, g_wo2h, H_, b_o2, g_p2, nullptr, H_,
              BN, blockIdx.x * 64, blockIdx.y * 128, 1);
}

__global__ void f3_kernel(const float* __restrict__ w_o3,
                          const float* __restrict__ b_o3,
                          float* __restrict__ out, int t) {
    int row = blockIdx.x;
    int w = threadIdx.x >> 5;
    int lane = threadIdx.x & 31;
    const float* pr = g_p2 + (size_t)row * H_;
    const float* wr = w_o3 + (size_t)w * H_;
    float s = 0.f;
    for (int j = lane; j < H_; j += 32) s += pr[j] * wr[j];
#pragma unroll
    for (int off = 16; off; off >>= 1) s += __shfl_down_sync(0xffffffffu, s, off);
    if (lane == 0) {
        int b = row / N_, n = row % N_;
        float v = g_ins[row * IN_ + w] + b_o3[w] + s;
        out[(((size_t)b * T_ + t) * N_ + n) * IN_ + w] = v;
        g_ins[row * IN_ + w] = v;
    }
}

// ---------------- launch ---------------------------------------------------------
extern "C" void kernel_launch(void* const* d_in, const int* in_sizes, int n_in,
                              void* d_out, int out_size) {
    const float* inputs = (const float*)d_in[0];
    const float* edges  = (const float*)d_in[1];
    const float* msg_w1 = (const float*)d_in[2];
    const float* msg_b1 = (const float*)d_in[3];
    const float* msg_w2 = (const float*)d_in[4];
    const float* msg_b2 = (const float*)d_in[5];
    const float* w_hr = (const float*)d_in[6];
    const float* w_hi = (const float*)d_in[7];
    const float* w_hh = (const float*)d_in[8];
    const float* w_ir = (const float*)d_in[9];
    const float* b_ir = (const float*)d_in[10];
    const float* w_ii = (const float*)d_in[11];
    const float* b_ii = (const float*)d_in[12];
    const float* w_in_ = (const float*)d_in[13];
    const float* b_in_ = (const float*)d_in[14];
    const float* w_o1 = (const float*)d_in[15];
    const float* b_o1 = (const float*)d_in[16];
    const float* w_o2 = (const float*)d_in[17];
    const float* b_o2 = (const float*)d_in[18];
    const float* w_o3 = (const float*)d_in[19];
    const float* b_o3 = (const float*)d_in[20];
    float* out = (float*)d_out;

    // one extra stream + two events (r14 configuration: passes teardown check)
    static cudaStream_t s2 = nullptr;
    static cudaEvent_t evF = nullptr, evJ = nullptr;
    if (s2 == nullptr) {
        cudaStreamCreateWithFlags(&s2, cudaStreamNonBlocking);
        cudaEventCreateWithFlags(&evF, cudaEventDisableTiming);
        cudaEventCreateWithFlags(&evJ, cudaEventDisableTiming);
    }

    cvt_weights<<<(6 * HH + 255) / 256, 256>>>(msg_w1, msg_w2, w_hr, w_hi, w_hh,
                                               w_o1, w_o2, msg_b1);
    init_kernel<<<(BN * H_ + 255) / 256, 256>>>(inputs);

    const int rowt = (BE + 63) / 64;  // 307
    for (int t = 0; t < T_; t++) {
        if (t > 0) {
            // output-MLP chain for step t-1 (reads hidden only) on s2
            cudaEventRecord(evF, 0);
            cudaStreamWaitEvent(s2, evF, 0);
            p1_tc<<<dim3(7, 2), 128, 0, s2>>>(b_o1);
            p2_tc<<<dim3(7, 2), 128, 0, s2>>>(b_o2);
            f3_kernel<<<BN, 192, 0, s2>>>(w_o3, b_o3, out, t - 1);
            cudaEventRecord(evJ, s2);
        }
        urus_tc<<<dim3(7, 2, 6), 128>>>(0);
        m1h_kernel<<<dim3(BE / 8, 3), 256>>>();
        msgs_f16_kernel<<<dim3(rowt, 2, 3), 128>>>(msg_b2, edges, t);
        agg_kernel<<<BN, 256>>>();
        gru_tc<<<dim3(7, 2, 3), 128>>>(0);
        if (t > 0) cudaStreamWaitEvent(0, evJ, 0);   // need g_ins from f3(t-1)
        gruew_kernel<<<(BN * H_ + 255) / 256, 256>>>(w_ir, b_ir, w_ii, b_ii, w_in_, b_in_);
    }
    // final step's output MLP
    p1_tc<<<dim3(7, 2), 128>>>(b_o1);
    p2_tc<<<dim3(7, 2), 128>>>(b_o2);
    f3_kernel<<<BN, 192>>>(w_o3, b_o3, out, T_ - 1);
}